// round 13
// baseline (speedup 1.0000x reference)
#include <cuda_runtime.h>
#include <cuda_bf16.h>
#include <cstdint>

// Problem constants
#define B_ 256
#define T_ 512          // TM1
#define N_ 256
#define H_ 256
#define G_ 1024         // 4*H
#define ENC_OFF ((size_t)B_ * T_ * N_)   // offset of input_encoded in d_out

// ---------------- device scratch (no cudaMalloc allowed) ----------------
__device__ float g_attn[B_ * N_];                      // softmax(x_scores)
__device__ float g_G1[(size_t)T_ * B_ * G_];           // gates pre-recurrence, [m=t*B+b][j]
__device__ float g_hbuf[2][B_ * H_];                   // ping-pong hidden state, [b][h]
__device__ __nv_bfloat16 g_Ahi[(size_t)T_ * B_ * N_];  // weighted, bf16 hi
__device__ __nv_bfloat16 g_Alo[(size_t)T_ * B_ * N_];  // weighted, bf16 lo
__device__ __nv_bfloat16 g_Bhi[G_ * N_];               // W_ih, bf16 hi
__device__ __nv_bfloat16 g_Blo[G_ * N_];               // W_ih, bf16 lo
// Group barrier: MONOTONIC counters (never reset -> no lost-arrival race),
// 128B padded per group, zeroed by k_attn at the start of every launch.
__device__ unsigned g_cnt_grp[256];

// ---------------- helpers ----------------
__device__ __forceinline__ float sigf(float x) {
    return __fdividef(1.f, 1.f + __expf(-x));
}
__device__ __forceinline__ float tanhfast(float x) {
    return __fdividef(2.f, 1.f + __expf(-2.f * x)) - 1.f;
}
__device__ __forceinline__ uint32_t smem_to_u32(const void* p) {
    uint32_t a;
    asm("{ .reg .u64 t; cvta.to.shared.u64 t, %1; cvt.u32.u64 %0, t; }" : "=r"(a) : "l"(p));
    return a;
}
__device__ __forceinline__ void split4(float4 v, uint2& hi, uint2& lo) {
    __nv_bfloat16 hx = __float2bfloat16(v.x);
    __nv_bfloat16 hy = __float2bfloat16(v.y);
    __nv_bfloat16 hz = __float2bfloat16(v.z);
    __nv_bfloat16 hw = __float2bfloat16(v.w);
    __nv_bfloat16 lx = __float2bfloat16(v.x - __bfloat162float(hx));
    __nv_bfloat16 ly = __float2bfloat16(v.y - __bfloat162float(hy));
    __nv_bfloat16 lz = __float2bfloat16(v.z - __bfloat162float(hz));
    __nv_bfloat16 lw = __float2bfloat16(v.w - __bfloat162float(hw));
    __nv_bfloat162 h01(hx, hy), h23(hz, hw), l01(lx, ly), l23(lz, lw);
    hi.x = *reinterpret_cast<uint32_t*>(&h01);
    hi.y = *reinterpret_cast<uint32_t*>(&h23);
    lo.x = *reinterpret_cast<uint32_t*>(&l01);
    lo.y = *reinterpret_cast<uint32_t*>(&l23);
}

// ---------------- cp.async helpers ----------------
#define CP_ASYNC16(dst, src) \
    asm volatile("cp.async.cg.shared.global [%0], [%1], 16;" :: "r"(dst), "l"(src) : "memory")
#define CP_COMMIT() asm volatile("cp.async.commit_group;" ::: "memory")
#define CP_WAIT1() asm volatile("cp.async.wait_group 1;" ::: "memory")
#define CP_WAIT0() asm volatile("cp.async.wait_group 0;" ::: "memory")

// ---------------- mma helpers (proven in K3) ----------------
#define LDM_X4(r0, r1, r2, r3, a) \
    asm volatile("ldmatrix.sync.aligned.m8n8.x4.shared.b16 {%0,%1,%2,%3}, [%4];" \
                 : "=r"(r0), "=r"(r1), "=r"(r2), "=r"(r3) : "r"(a))
#define MMA16816(c, a, b) \
    asm volatile("mma.sync.aligned.m16n8k16.row.col.f32.bf16.bf16.f32 " \
                 "{%0,%1,%2,%3}, {%4,%5,%6,%7}, {%8,%9}, {%0,%1,%2,%3};" \
                 : "+f"((c)[0]), "+f"((c)[1]), "+f"((c)[2]), "+f"((c)[3]) \
                 : "r"((a)[0]), "r"((a)[1]), "r"((a)[2]), "r"((a)[3]), "r"((b)[0]), "r"((b)[1]))

// ---------------- K1: x_scores + softmax -> attn, zero h buffer + counters ----
__global__ void k_attn(const float* __restrict__ in, const float* __restrict__ attn_w) {
    __shared__ float wx[T_];
    __shared__ float red[N_];
    int b = blockIdx.x;
    int n = threadIdx.x;

    if (b == 0) g_cnt_grp[n] = 0;    // reset group-barrier counters every launch

    wx[n]       = attn_w[2 * H_ + n];
    wx[n + 256] = attn_w[2 * H_ + 256 + n];
    __syncthreads();

    const float* p = in + (size_t)b * T_ * N_ + n;
    float acc = 0.f;
#pragma unroll 8
    for (int t = 0; t < T_; ++t)
        acc = fmaf(p[(size_t)t * N_], wx[t], acc);

    red[n] = acc;
    __syncthreads();
    for (int s = 128; s > 0; s >>= 1) {
        if (n < s) red[n] = fmaxf(red[n], red[n + s]);
        __syncthreads();
    }
    float mx = red[0];
    __syncthreads();
    float e = expf(acc - mx);
    red[n] = e;
    __syncthreads();
    for (int s = 128; s > 0; s >>= 1) {
        if (n < s) red[n] += red[n + s];
        __syncthreads();
    }
    g_attn[b * N_ + n] = e / red[0];
    g_hbuf[0][b * N_ + n] = 0.f;
}

// ---------------- K2: weighted = attn * x -> out region 0 + bf16 hi/lo ---------
__global__ void k_weighted(const float* __restrict__ in, float* __restrict__ out) {
    int blk = blockIdx.x;            // b*T_ + t
    int b = blk >> 9;
    int t = blk & 511;
    int n = threadIdx.x;
    size_t idx = (size_t)blk * N_ + n;
    float w = g_attn[b * N_ + n] * in[idx];
    out[idx] = w;
    size_t m = (size_t)t * B_ + b;   // GEMM row index
    __nv_bfloat16 hi = __float2bfloat16(w);
    __nv_bfloat16 lo = __float2bfloat16(w - __bfloat162float(hi));
    g_Ahi[m * N_ + n] = hi;
    g_Alo[m * N_ + n] = lo;
}

// ---------------- K2b: W_ih -> bf16 hi/lo ----------------
__global__ void k_convB(const float* __restrict__ Wih) {
    int j = blockIdx.x;
    int k = threadIdx.x;
    float v = Wih[(size_t)j * N_ + k];
    __nv_bfloat16 hi = __float2bfloat16(v);
    __nv_bfloat16 lo = __float2bfloat16(v - __bfloat162float(hi));
    g_Bhi[j * N_ + k] = hi;
    g_Blo[j * N_ + k] = lo;
}

// ---------------- K3: mma.sync bf16 split GEMM, cp.async double-buffered -------
// (unchanged — proven at 517us)
#define TILE_BYTES 16384           // 128 x 64 bf16

__global__ void __launch_bounds__(256) k_gemm_mma(
        const float* __restrict__ b_ih, const float* __restrict__ b_hh) {
    __shared__ __align__(16) __nv_bfloat16 Sb[4 * 128 * 64];   // 64 KB
    __shared__ float bias_s[128];

    int tid = threadIdx.x;
    int wid = tid >> 5;
    int lane = tid & 31;
    int nt = blockIdx.x;             // 0..7  gate tile
    int mt = blockIdx.y;             // 0..1023 m tile
    int j0 = nt * 128;
    int wm = wid >> 2;               // 0..1
    int wn = wid & 3;                // 0..3

    if (tid < 128) bias_s[tid] = b_ih[j0 + tid] + b_hh[j0 + tid];

    uint32_t s_base = smem_to_u32(Sb);

    int st_r[4], st_sw[4];
#pragma unroll
    for (int it = 0; it < 4; ++it) {
        int idx = tid + it * 256;        // 0..1023
        int r = idx >> 3;
        int kg = idx & 7;
        st_r[it] = r * 32 + kg;
        st_sw[it] = r * 8 + (kg ^ (r & 7));
    }

    const __nv_bfloat16* a_srcs[3] = {g_Ahi, g_Alo, g_Ahi};
    const __nv_bfloat16* b_srcs[3] = {g_Bhi, g_Bhi, g_Blo};

#define ISSUE_CHUNK(ch) do { \
        int _term = (ch) >> 2; \
        int _kk0 = ((ch) & 3) * 64; \
        const char* _gA = (const char*)(a_srcs[_term] + (size_t)mt * 128 * N_ + _kk0); \
        const char* _gB = (const char*)(b_srcs[_term] + (size_t)j0 * N_ + _kk0); \
        uint32_t _sa = s_base + ((ch) & 1) * 2u * TILE_BYTES; \
        uint32_t _sb = _sa + TILE_BYTES; \
        _Pragma("unroll") \
        for (int _it = 0; _it < 4; ++_it) { \
            CP_ASYNC16(_sa + (uint32_t)st_sw[_it] * 16u, _gA + (size_t)st_r[_it] * 16); \
            CP_ASYNC16(_sb + (uint32_t)st_sw[_it] * 16u, _gB + (size_t)st_r[_it] * 16); \
        } \
        CP_COMMIT(); \
    } while (0)

    int a_r15 = lane & 15;
    int a_kh  = lane >> 4;
    int b_row = ((lane & 16) >> 1) + (lane & 7);
    int b_kh  = (lane >> 3) & 1;

    float acc[4][4][4];
#pragma unroll
    for (int i = 0; i < 4; ++i)
#pragma unroll
        for (int j = 0; j < 4; ++j)
#pragma unroll
            for (int q = 0; q < 4; ++q) acc[i][j][q] = 0.f;

    ISSUE_CHUNK(0);

    for (int ch = 0; ch < 12; ++ch) {
        if (ch + 1 < 12) {
            ISSUE_CHUNK(ch + 1);
            CP_WAIT1();
        } else {
            CP_WAIT0();
        }
        __syncthreads();

        uint32_t as_base = s_base + (ch & 1) * 2u * TILE_BYTES;
        uint32_t bs_base = as_base + TILE_BYTES;

#pragma unroll
        for (int ks = 0; ks < 4; ++ks) {
            uint32_t afr[4][4];
            uint32_t bfr[4][2];
#pragma unroll
            for (int tm = 0; tm < 4; ++tm) {
                int row = wm * 64 + tm * 16 + a_r15;
                int c = (2 * ks + a_kh) ^ (a_r15 & 7);
                uint32_t addr = as_base + (uint32_t)(row * 64 + c * 8) * 2u;
                LDM_X4(afr[tm][0], afr[tm][1], afr[tm][2], afr[tm][3], addr);
            }
#pragma unroll
            for (int tn2 = 0; tn2 < 2; ++tn2) {
                int row = wn * 32 + tn2 * 16 + b_row;
                int c = (2 * ks + b_kh) ^ (b_row & 7);
                uint32_t addr = bs_base + (uint32_t)(row * 64 + c * 8) * 2u;
                uint32_t r0, r1, r2, r3;
                LDM_X4(r0, r1, r2, r3, addr);
                bfr[tn2 * 2 + 0][0] = r0; bfr[tn2 * 2 + 0][1] = r1;
                bfr[tn2 * 2 + 1][0] = r2; bfr[tn2 * 2 + 1][1] = r3;
            }
#pragma unroll
            for (int tm = 0; tm < 4; ++tm)
#pragma unroll
                for (int tn = 0; tn < 4; ++tn)
                    MMA16816(acc[tm][tn], afr[tm], bfr[tn]);
        }
        __syncthreads();
    }

    int qr = lane >> 2;
    int qc = (lane & 3) * 2;
#pragma unroll
    for (int tm = 0; tm < 4; ++tm) {
#pragma unroll
        for (int tn = 0; tn < 4; ++tn) {
            int colt = wn * 32 + tn * 8 + qc;
            size_t m0 = (size_t)mt * 128 + wm * 64 + tm * 16 + qr;
            float bx = bias_s[colt], by = bias_s[colt + 1];
            float2 v0 = make_float2(acc[tm][tn][0] + bx, acc[tm][tn][1] + by);
            float2 v1 = make_float2(acc[tm][tn][2] + bx, acc[tm][tn][3] + by);
            *(float2*)(g_G1 + m0 * G_ + j0 + colt) = v0;
            *(float2*)(g_G1 + (m0 + 8) * G_ + j0 + colt) = v1;
        }
    }
}

// ---------------- K4: persistent recurrence, tensor-core inner GEMM ------------
// 256 threads = 8 warps (2 warps/SMSP for LDSM latency hiding).
// Warp grid 2m x 4n: warp tile m16 x n16 -> per (kc,ks): 2 A-LDSM + 2 B-LDSM
// + 6 HMMA (3-term bf16 split, proven fragments from K3/R12).
// CTA = 32 batches x 16 hid (64 gate cols, order n = hid*4 + q).
// Group barrier: 16 CTAs sharing the batch tile, monotonic counters (proven R11).
// SMEM bytes: WHI 32K | WLO 32K | AHI 16K | ALO 16K | gbuf 8.7K
#define S_WHI 0
#define S_WLO 32768
#define S_AHI 65536
#define S_ALO 81920
#define S_GB  98304
#define S_TOT 107008

__global__ void __launch_bounds__(256, 1) k_recur(
        const float* __restrict__ Whh, float* __restrict__ out_enc) {
    extern __shared__ __align__(16) char smem[];
    uint32_t s_base = smem_to_u32(smem);
    float* gbuf = (float*)(smem + S_GB);      // [32][68] fp32 gate bounce

    int tid = threadIdx.x;            // 256 = 8 warps
    int lane = tid & 31;
    int wid = tid >> 5;
    int wm = wid & 1;                 // m half (16 batches)
    int wn = wid >> 1;                // n quarter (16 gate cols)
    int b0 = blockIdx.x * 32;
    int h0 = blockIdx.y * 16;
    int grp = blockIdx.x;

    // Build W bf16 hi/lo subtiles once. Subtile kc: [64 rows][64 k], row n = hid*4+q,
    // 128B rows, XOR-swizzled 16B granules (same scheme as K3 tiles).
    for (int idx = tid; idx < 4096; idx += 256) {
        int n = idx >> 6;             // 0..63
        int kq = idx & 63;            // float4 index along k
        int hid = n >> 2, q = n & 3;
        float4 v = *(const float4*)(Whh + (size_t)(q * H_ + h0 + hid) * N_ + kq * 4);
        uint2 hi, lo;
        split4(v, hi, lo);
        int kc = kq >> 4, kk = kq & 15, kg = kk >> 1, half = kk & 1;
        uint32_t off = (uint32_t)(kc * 8192 + n * 128 + ((kg ^ (n & 7)) << 4) + half * 8);
        *(uint2*)(smem + S_WHI + off) = hi;
        *(uint2*)(smem + S_WLO + off) = lo;
    }

    // ldmatrix lane precompute (identical to K3)
    int a_r15 = lane & 15;
    int a_kh  = lane >> 4;
    int b_row = ((lane & 16) >> 1) + (lane & 7);
    int b_kh  = (lane >> 3) & 1;

    // epilogue mapping: thread owns batch eb, hid pair [eh2*2, eh2*2+1]
    int eb  = tid & 31;
    int eh2 = tid >> 5;               // 0..7

    float creg[2] = {0.f, 0.f};
    __syncthreads();

    // G1 prefetch for t=0: per gate q a float2 (hid pair)
    float2 g1s[4];
#pragma unroll
    for (int q = 0; q < 4; ++q)
        g1s[q] = __ldcg((const float2*)(g_G1 + ((size_t)(b0 + eb)) * G_ + q * 256 + h0 + eh2 * 2));

    for (int t = 0; t < T_; ++t) {
        // stage h -> bf16 hi/lo A subtiles (kc: [32 rows b][64 k], 128B rows)
        const float4* gh4 = (const float4*)(g_hbuf[t & 1]) + (size_t)b0 * 64;
#pragma unroll
        for (int it = 0; it < 8; ++it) {
            int idx = tid + it * 256;     // 0..2047
            int b = idx >> 6;             // 0..31
            int kq = idx & 63;
            float4 v = __ldcg(gh4 + b * 64 + kq);
            uint2 hi, lo;
            split4(v, hi, lo);
            int kc = kq >> 4, kk = kq & 15, kg = kk >> 1, half = kk & 1;
            uint32_t off = (uint32_t)(kc * 4096 + b * 128 + ((kg ^ (b & 7)) << 4) + half * 8);
            *(uint2*)(smem + S_AHI + off) = hi;
            *(uint2*)(smem + S_ALO + off) = lo;
        }
        __syncthreads();

        // D = h @ W^T, 3-term bf16 split, warp tile m16 x n16
        float cfr[2][4];
#pragma unroll
        for (int tn = 0; tn < 2; ++tn)
#pragma unroll
            for (int q = 0; q < 4; ++q) cfr[tn][q] = 0.f;

#pragma unroll
        for (int kc = 0; kc < 4; ++kc) {
            uint32_t aHiB = s_base + S_AHI + kc * 4096;
            uint32_t aLoB = s_base + S_ALO + kc * 4096;
            uint32_t bHiB = s_base + S_WHI + kc * 8192;
            uint32_t bLoB = s_base + S_WLO + kc * 8192;
#pragma unroll
            for (int ks = 0; ks < 4; ++ks) {
                uint32_t ahi[4], alo[4], bhi[2][2], blo[2][2];
                int ac = (2 * ks + a_kh) ^ (a_r15 & 7);
                uint32_t aoff = (uint32_t)((wm * 16 + a_r15) * 128 + ac * 16);
                LDM_X4(ahi[0], ahi[1], ahi[2], ahi[3], aHiB + aoff);
                LDM_X4(alo[0], alo[1], alo[2], alo[3], aLoB + aoff);
                {
                    int row = wn * 16 + b_row;
                    int bc = (2 * ks + b_kh) ^ (b_row & 7);
                    uint32_t boff = (uint32_t)(row * 128 + bc * 16);
                    uint32_t r0, r1, r2, r3;
                    LDM_X4(r0, r1, r2, r3, bHiB + boff);
                    bhi[0][0] = r0; bhi[0][1] = r1;
                    bhi[1][0] = r2; bhi[1][1] = r3;
                    LDM_X4(r0, r1, r2, r3, bLoB + boff);
                    blo[0][0] = r0; blo[0][1] = r1;
                    blo[1][0] = r2; blo[1][1] = r3;
                }
#pragma unroll
                for (int tn = 0; tn < 2; ++tn) MMA16816(cfr[tn], ahi, bhi[tn]);
#pragma unroll
                for (int tn = 0; tn < 2; ++tn) MMA16816(cfr[tn], alo, bhi[tn]);
#pragma unroll
                for (int tn = 0; tn < 2; ++tn) MMA16816(cfr[tn], ahi, blo[tn]);
            }
        }

        // scatter c-frags to gate bounce buffer
        int qr = lane >> 2, qc = (lane & 3) * 2;
#pragma unroll
        for (int tn = 0; tn < 2; ++tn) {
            int col = wn * 16 + tn * 8 + qc;
            int r0 = wm * 16 + qr;
            *(float2*)&gbuf[r0 * 68 + col] = make_float2(cfr[tn][0], cfr[tn][1]);
            *(float2*)&gbuf[(r0 + 8) * 68 + col] = make_float2(cfr[tn][2], cfr[tn][3]);
        }
        __syncthreads();

        // LSTM epilogue: thread reads 8 contiguous gates (2 hid x 4 q)
        float4 v0 = *(const float4*)&gbuf[eb * 68 + eh2 * 8];
        float4 v1 = *(const float4*)&gbuf[eb * 68 + eh2 * 8 + 4];
        float hn0, hn1;
        {
            float cc = fmaf(sigf(v0.y + g1s[1].x), creg[0],
                            sigf(v0.x + g1s[0].x) * tanhfast(v0.z + g1s[2].x));
            creg[0] = cc;
            hn0 = sigf(v0.w + g1s[3].x) * tanhfast(cc);
        }
        {
            float cc = fmaf(sigf(v1.y + g1s[1].y), creg[1],
                            sigf(v1.x + g1s[0].y) * tanhfast(v1.z + g1s[2].y));
            creg[1] = cc;
            hn1 = sigf(v1.w + g1s[3].y) * tanhfast(cc);
        }
        float2 hv = make_float2(hn0, hn1);
        __stcg((float2*)(g_hbuf[(t + 1) & 1] + (size_t)(b0 + eb) * H_ + h0 + eh2 * 2), hv);
        *(float2*)(out_enc + ((size_t)(b0 + eb) * T_ + t) * H_ + h0 + eh2 * 2) = hv;

        if (t + 1 < T_) {
            // prefetch G1 for t+1 (loads fly during barrier)
#pragma unroll
            for (int q = 0; q < 4; ++q)
                g1s[q] = __ldcg((const float2*)(g_G1 + ((size_t)(t + 1) * B_ + b0 + eb) * G_ + q * 256 + h0 + eh2 * 2));
            // ---- group barrier (16 CTAs, monotonic counter — proven R11) ----
            __threadfence();
            __syncthreads();
            if (tid == 0) atomicAdd(&g_cnt_grp[grp * 32], 1u);
            unsigned target = (unsigned)(t + 1) * 16u;
            volatile unsigned* cp = &g_cnt_grp[grp * 32];
            while (*cp < target) { __nanosleep(32); }
            __threadfence();
        }
    }
}

// ---------------- launch ----------------
extern "C" void kernel_launch(void* const* d_in, const int* in_sizes, int n_in,
                              void* d_out, int out_size) {
    const float* input  = (const float*)d_in[0];
    const float* W_ih   = (const float*)d_in[1];
    const float* W_hh   = (const float*)d_in[2];
    const float* b_ih   = (const float*)d_in[3];
    const float* b_hh   = (const float*)d_in[4];
    const float* attn_w = (const float*)d_in[5];
    float* out = (float*)d_out;

    cudaFuncSetAttribute(k_recur, cudaFuncAttributeMaxDynamicSharedMemorySize, S_TOT);

    // K1: attention weights (+ zero h state, zero group counters)
    k_attn<<<B_, N_>>>(input, attn_w);
    // K2: weighted input -> output region 0 + bf16 hi/lo staging
    k_weighted<<<B_ * T_, N_>>>(input, out);
    // K2b: W_ih bf16 hi/lo
    k_convB<<<G_, N_>>>(W_ih);
    // K3: HMMA split-bf16 GEMM into g_G1, cp.async double-buffered
    dim3 g3(8, 1024);
    k_gemm_mma<<<g3, 256>>>(b_ih, b_hh);
    // K4: persistent recurrence -> output region 1 (8-warp tensor-core GEMM)
    dim3 g4(8, 16);
    k_recur<<<g4, 256, S_TOT>>>(W_hh, out + ENC_OFF);
}

// round 14
// speedup vs baseline: 1.1778x; 1.1778x over previous
#include <cuda_runtime.h>
#include <cuda_bf16.h>
#include <cstdint>

// Problem constants
#define B_ 256
#define T_ 512          // TM1
#define N_ 256
#define H_ 256
#define G_ 1024         // 4*H
#define ENC_OFF ((size_t)B_ * T_ * N_)   // offset of input_encoded in d_out

// ---------------- device scratch (no cudaMalloc allowed) ----------------
__device__ float g_attn[B_ * N_];                      // softmax(x_scores)
__device__ float g_G1[(size_t)T_ * B_ * G_];           // gates pre-recurrence, [m=t*B+b][j]
__device__ __nv_bfloat16 g_hbf[2][2][B_ * H_];         // h ping-pong x {hi,lo} planes, [b][h]
__device__ __nv_bfloat16 g_Ahi[(size_t)T_ * B_ * N_];  // weighted, bf16 hi
__device__ __nv_bfloat16 g_Alo[(size_t)T_ * B_ * N_];  // weighted, bf16 lo
__device__ __nv_bfloat16 g_Bhi[G_ * N_];               // W_ih, bf16 hi
__device__ __nv_bfloat16 g_Blo[G_ * N_];               // W_ih, bf16 lo
// Group barrier: MONOTONIC counters (never reset -> no lost-arrival race),
// 128B padded per group, zeroed by k_attn at the start of every launch.
__device__ unsigned g_cnt_grp[256];

// ---------------- helpers ----------------
__device__ __forceinline__ float sigf(float x) {
    return __fdividef(1.f, 1.f + __expf(-x));
}
__device__ __forceinline__ float tanhfast(float x) {
    return __fdividef(2.f, 1.f + __expf(-2.f * x)) - 1.f;
}
__device__ __forceinline__ uint32_t smem_to_u32(const void* p) {
    uint32_t a;
    asm("{ .reg .u64 t; cvta.to.shared.u64 t, %1; cvt.u32.u64 %0, t; }" : "=r"(a) : "l"(p));
    return a;
}
__device__ __forceinline__ void split4(float4 v, uint2& hi, uint2& lo) {
    __nv_bfloat16 hx = __float2bfloat16(v.x);
    __nv_bfloat16 hy = __float2bfloat16(v.y);
    __nv_bfloat16 hz = __float2bfloat16(v.z);
    __nv_bfloat16 hw = __float2bfloat16(v.w);
    __nv_bfloat16 lx = __float2bfloat16(v.x - __bfloat162float(hx));
    __nv_bfloat16 ly = __float2bfloat16(v.y - __bfloat162float(hy));
    __nv_bfloat16 lz = __float2bfloat16(v.z - __bfloat162float(hz));
    __nv_bfloat16 lw = __float2bfloat16(v.w - __bfloat162float(hw));
    __nv_bfloat162 h01(hx, hy), h23(hz, hw), l01(lx, ly), l23(lz, lw);
    hi.x = *reinterpret_cast<uint32_t*>(&h01);
    hi.y = *reinterpret_cast<uint32_t*>(&h23);
    lo.x = *reinterpret_cast<uint32_t*>(&l01);
    lo.y = *reinterpret_cast<uint32_t*>(&l23);
}

// ---------------- cp.async helpers ----------------
#define CP_ASYNC16(dst, src) \
    asm volatile("cp.async.cg.shared.global [%0], [%1], 16;" :: "r"(dst), "l"(src) : "memory")
#define CP_COMMIT() asm volatile("cp.async.commit_group;" ::: "memory")
#define CP_WAIT1() asm volatile("cp.async.wait_group 1;" ::: "memory")
#define CP_WAIT0() asm volatile("cp.async.wait_group 0;" ::: "memory")

// ---------------- mma helpers (proven in K3) ----------------
#define LDM_X4(r0, r1, r2, r3, a) \
    asm volatile("ldmatrix.sync.aligned.m8n8.x4.shared.b16 {%0,%1,%2,%3}, [%4];" \
                 : "=r"(r0), "=r"(r1), "=r"(r2), "=r"(r3) : "r"(a))
#define MMA16816(c, a, b) \
    asm volatile("mma.sync.aligned.m16n8k16.row.col.f32.bf16.bf16.f32 " \
                 "{%0,%1,%2,%3}, {%4,%5,%6,%7}, {%8,%9}, {%0,%1,%2,%3};" \
                 : "+f"((c)[0]), "+f"((c)[1]), "+f"((c)[2]), "+f"((c)[3]) \
                 : "r"((a)[0]), "r"((a)[1]), "r"((a)[2]), "r"((a)[3]), "r"((b)[0]), "r"((b)[1]))

// ---------------- K1: x_scores + softmax -> attn, zero h planes + counters ----
__global__ void k_attn(const float* __restrict__ in, const float* __restrict__ attn_w) {
    __shared__ float wx[T_];
    __shared__ float red[N_];
    int b = blockIdx.x;
    int n = threadIdx.x;

    if (b == 0) g_cnt_grp[n] = 0;    // reset group-barrier counters every launch

    wx[n]       = attn_w[2 * H_ + n];
    wx[n + 256] = attn_w[2 * H_ + 256 + n];
    __syncthreads();

    const float* p = in + (size_t)b * T_ * N_ + n;
    float acc = 0.f;
#pragma unroll 8
    for (int t = 0; t < T_; ++t)
        acc = fmaf(p[(size_t)t * N_], wx[t], acc);

    red[n] = acc;
    __syncthreads();
    for (int s = 128; s > 0; s >>= 1) {
        if (n < s) red[n] = fmaxf(red[n], red[n + s]);
        __syncthreads();
    }
    float mx = red[0];
    __syncthreads();
    float e = expf(acc - mx);
    red[n] = e;
    __syncthreads();
    for (int s = 128; s > 0; s >>= 1) {
        if (n < s) red[n] += red[n + s];
        __syncthreads();
    }
    g_attn[b * N_ + n] = e / red[0];
    // zero initial hidden-state bf16 planes (bf16 zero == 0x0000)
    g_hbf[0][0][b * N_ + n] = __float2bfloat16(0.f);
    g_hbf[0][1][b * N_ + n] = __float2bfloat16(0.f);
}

// ---------------- K2: weighted = attn * x -> out region 0 + bf16 hi/lo ---------
__global__ void k_weighted(const float* __restrict__ in, float* __restrict__ out) {
    int blk = blockIdx.x;            // b*T_ + t
    int b = blk >> 9;
    int t = blk & 511;
    int n = threadIdx.x;
    size_t idx = (size_t)blk * N_ + n;
    float w = g_attn[b * N_ + n] * in[idx];
    out[idx] = w;
    size_t m = (size_t)t * B_ + b;   // GEMM row index
    __nv_bfloat16 hi = __float2bfloat16(w);
    __nv_bfloat16 lo = __float2bfloat16(w - __bfloat162float(hi));
    g_Ahi[m * N_ + n] = hi;
    g_Alo[m * N_ + n] = lo;
}

// ---------------- K2b: W_ih -> bf16 hi/lo ----------------
__global__ void k_convB(const float* __restrict__ Wih) {
    int j = blockIdx.x;
    int k = threadIdx.x;
    float v = Wih[(size_t)j * N_ + k];
    __nv_bfloat16 hi = __float2bfloat16(v);
    __nv_bfloat16 lo = __float2bfloat16(v - __bfloat162float(hi));
    g_Bhi[j * N_ + k] = hi;
    g_Blo[j * N_ + k] = lo;
}

// ---------------- K3: mma.sync bf16 split GEMM, cp.async double-buffered -------
// (unchanged — proven at 517us)
#define TILE_BYTES 16384           // 128 x 64 bf16

__global__ void __launch_bounds__(256) k_gemm_mma(
        const float* __restrict__ b_ih, const float* __restrict__ b_hh) {
    __shared__ __align__(16) __nv_bfloat16 Sb[4 * 128 * 64];   // 64 KB
    __shared__ float bias_s[128];

    int tid = threadIdx.x;
    int wid = tid >> 5;
    int lane = tid & 31;
    int nt = blockIdx.x;             // 0..7  gate tile
    int mt = blockIdx.y;             // 0..1023 m tile
    int j0 = nt * 128;
    int wm = wid >> 2;               // 0..1
    int wn = wid & 3;                // 0..3

    if (tid < 128) bias_s[tid] = b_ih[j0 + tid] + b_hh[j0 + tid];

    uint32_t s_base = smem_to_u32(Sb);

    int st_r[4], st_sw[4];
#pragma unroll
    for (int it = 0; it < 4; ++it) {
        int idx = tid + it * 256;        // 0..1023
        int r = idx >> 3;
        int kg = idx & 7;
        st_r[it] = r * 32 + kg;
        st_sw[it] = r * 8 + (kg ^ (r & 7));
    }

    const __nv_bfloat16* a_srcs[3] = {g_Ahi, g_Alo, g_Ahi};
    const __nv_bfloat16* b_srcs[3] = {g_Bhi, g_Bhi, g_Blo};

#define ISSUE_CHUNK(ch) do { \
        int _term = (ch) >> 2; \
        int _kk0 = ((ch) & 3) * 64; \
        const char* _gA = (const char*)(a_srcs[_term] + (size_t)mt * 128 * N_ + _kk0); \
        const char* _gB = (const char*)(b_srcs[_term] + (size_t)j0 * N_ + _kk0); \
        uint32_t _sa = s_base + ((ch) & 1) * 2u * TILE_BYTES; \
        uint32_t _sb = _sa + TILE_BYTES; \
        _Pragma("unroll") \
        for (int _it = 0; _it < 4; ++_it) { \
            CP_ASYNC16(_sa + (uint32_t)st_sw[_it] * 16u, _gA + (size_t)st_r[_it] * 16); \
            CP_ASYNC16(_sb + (uint32_t)st_sw[_it] * 16u, _gB + (size_t)st_r[_it] * 16); \
        } \
        CP_COMMIT(); \
    } while (0)

    int a_r15 = lane & 15;
    int a_kh  = lane >> 4;
    int b_row = ((lane & 16) >> 1) + (lane & 7);
    int b_kh  = (lane >> 3) & 1;

    float acc[4][4][4];
#pragma unroll
    for (int i = 0; i < 4; ++i)
#pragma unroll
        for (int j = 0; j < 4; ++j)
#pragma unroll
            for (int q = 0; q < 4; ++q) acc[i][j][q] = 0.f;

    ISSUE_CHUNK(0);

    for (int ch = 0; ch < 12; ++ch) {
        if (ch + 1 < 12) {
            ISSUE_CHUNK(ch + 1);
            CP_WAIT1();
        } else {
            CP_WAIT0();
        }
        __syncthreads();

        uint32_t as_base = s_base + (ch & 1) * 2u * TILE_BYTES;
        uint32_t bs_base = as_base + TILE_BYTES;

#pragma unroll
        for (int ks = 0; ks < 4; ++ks) {
            uint32_t afr[4][4];
            uint32_t bfr[4][2];
#pragma unroll
            for (int tm = 0; tm < 4; ++tm) {
                int row = wm * 64 + tm * 16 + a_r15;
                int c = (2 * ks + a_kh) ^ (a_r15 & 7);
                uint32_t addr = as_base + (uint32_t)(row * 64 + c * 8) * 2u;
                LDM_X4(afr[tm][0], afr[tm][1], afr[tm][2], afr[tm][3], addr);
            }
#pragma unroll
            for (int tn2 = 0; tn2 < 2; ++tn2) {
                int row = wn * 32 + tn2 * 16 + b_row;
                int c = (2 * ks + b_kh) ^ (b_row & 7);
                uint32_t addr = bs_base + (uint32_t)(row * 64 + c * 8) * 2u;
                uint32_t r0, r1, r2, r3;
                LDM_X4(r0, r1, r2, r3, addr);
                bfr[tn2 * 2 + 0][0] = r0; bfr[tn2 * 2 + 0][1] = r1;
                bfr[tn2 * 2 + 1][0] = r2; bfr[tn2 * 2 + 1][1] = r3;
            }
#pragma unroll
            for (int tm = 0; tm < 4; ++tm)
#pragma unroll
                for (int tn = 0; tn < 4; ++tn)
                    MMA16816(acc[tm][tn], afr[tm], bfr[tn]);
        }
        __syncthreads();
    }

    int qr = lane >> 2;
    int qc = (lane & 3) * 2;
#pragma unroll
    for (int tm = 0; tm < 4; ++tm) {
#pragma unroll
        for (int tn = 0; tn < 4; ++tn) {
            int colt = wn * 32 + tn * 8 + qc;
            size_t m0 = (size_t)mt * 128 + wm * 64 + tm * 16 + qr;
            float bx = bias_s[colt], by = bias_s[colt + 1];
            float2 v0 = make_float2(acc[tm][tn][0] + bx, acc[tm][tn][1] + by);
            float2 v1 = make_float2(acc[tm][tn][2] + bx, acc[tm][tn][3] + by);
            *(float2*)(g_G1 + m0 * G_ + j0 + colt) = v0;
            *(float2*)(g_G1 + (m0 + 8) * G_ + j0 + colt) = v1;
        }
    }
}

// ---------------- K4: persistent recurrence, tensor-core inner GEMM ------------
// R12 structure (128 threads, 4 warps 2m x 2n, proven 3157us) with ONE change:
// h is stored by the producer as bf16 hi/lo planes, so per-step A staging is
// pure cp.async 16B copies into the swizzled subtile layout (no LDG/split/STS).
// CTA = 32 batches x 16 hid (64 gate cols, n = hid*4 + q).
// Group barrier: 16 CTAs sharing the batch tile, monotonic counters (proven R11).
// SMEM bytes: WHI 32K | WLO 32K | AHI 16K | ALO 16K | gbuf 8.7K
#define S_WHI 0
#define S_WLO 32768
#define S_AHI 65536
#define S_ALO 81920
#define S_GB  98304
#define S_TOT 107008

__global__ void __launch_bounds__(128, 1) k_recur(
        const float* __restrict__ Whh, float* __restrict__ out_enc) {
    extern __shared__ __align__(16) char smem[];
    uint32_t s_base = smem_to_u32(smem);
    float* gbuf = (float*)(smem + S_GB);      // [32][68] fp32 gate bounce

    int tid = threadIdx.x;            // 128 = 4 warps
    int lane = tid & 31;
    int wid = tid >> 5;
    int wm = wid & 1;                 // m half (16 batches)
    int wn = wid >> 1;                // n half (32 gate cols)
    int b0 = blockIdx.x * 32;
    int h0 = blockIdx.y * 16;
    int grp = blockIdx.x;

    // Build W bf16 hi/lo subtiles once. Subtile kc: [64 rows][64 k], row n = hid*4+q,
    // 128B rows, XOR-swizzled 16B granules (same scheme as K3 tiles).
    for (int idx = tid; idx < 4096; idx += 128) {
        int n = idx >> 6;             // 0..63
        int kq = idx & 63;            // float4 index along k
        int hid = n >> 2, q = n & 3;
        float4 v = *(const float4*)(Whh + (size_t)(q * H_ + h0 + hid) * N_ + kq * 4);
        uint2 hi, lo;
        split4(v, hi, lo);
        int kc = kq >> 4, kk = kq & 15, kg = kk >> 1, half = kk & 1;
        uint32_t off = (uint32_t)(kc * 8192 + n * 128 + ((kg ^ (n & 7)) << 4) + half * 8);
        *(uint2*)(smem + S_WHI + off) = hi;
        *(uint2*)(smem + S_WLO + off) = lo;
    }

    // ldmatrix lane precompute (identical to K3)
    int a_r15 = lane & 15;
    int a_kh  = lane >> 4;
    int b_row = ((lane & 16) >> 1) + (lane & 7);
    int b_kh  = (lane >> 3) & 1;

    // cp.async staging indices: 1024 16B granules per plane, 8 per thread
    int stg_b[8], stg_kc[8], stg_kg[8];
#pragma unroll
    for (int it = 0; it < 8; ++it) {
        int idx = tid + it * 128;     // 0..1023
        stg_b[it] = idx >> 5;
        stg_kc[it] = (idx >> 3) & 3;
        stg_kg[it] = idx & 7;
    }

    // epilogue mapping: thread owns batch eb, hids [eh4*4, eh4*4+4)
    int eb  = tid & 31;
    int eh4 = tid >> 5;

    float creg[4] = {0.f, 0.f, 0.f, 0.f};
    __syncthreads();

    // G1 prefetch for t=0: g1s[q*4+j]
    float g1s[16];
#pragma unroll
    for (int q = 0; q < 4; ++q) {
        float4 v = __ldcg((const float4*)(g_G1 + ((size_t)(b0 + eb)) * G_ + q * 256 + h0 + eh4 * 4));
        g1s[q * 4 + 0] = v.x; g1s[q * 4 + 1] = v.y;
        g1s[q * 4 + 2] = v.z; g1s[q * 4 + 3] = v.w;
    }

    for (int t = 0; t < T_; ++t) {
        // stage h bf16 hi/lo planes -> swizzled A subtiles via cp.async (pure copy)
        const char* srcHi = (const char*)(g_hbf[t & 1][0] + (size_t)b0 * H_);
        const char* srcLo = (const char*)(g_hbf[t & 1][1] + (size_t)b0 * H_);
#pragma unroll
        for (int it = 0; it < 8; ++it) {
            int b = stg_b[it], kc = stg_kc[it], kg = stg_kg[it];
            uint32_t doff = (uint32_t)(kc * 4096 + b * 128 + ((kg ^ (b & 7)) << 4));
            size_t soff = (size_t)b * 512 + kc * 128 + kg * 16;
            CP_ASYNC16(s_base + S_AHI + doff, srcHi + soff);
            CP_ASYNC16(s_base + S_ALO + doff, srcLo + soff);
        }
        CP_COMMIT();
        CP_WAIT0();
        __syncthreads();

        // D = h @ W^T, 3-term bf16 split, warp tile m16 x n32
        float cfr[4][4];
#pragma unroll
        for (int tn = 0; tn < 4; ++tn)
#pragma unroll
            for (int q = 0; q < 4; ++q) cfr[tn][q] = 0.f;

#pragma unroll
        for (int kc = 0; kc < 4; ++kc) {
            uint32_t aHiB = s_base + S_AHI + kc * 4096;
            uint32_t aLoB = s_base + S_ALO + kc * 4096;
            uint32_t bHiB = s_base + S_WHI + kc * 8192;
            uint32_t bLoB = s_base + S_WLO + kc * 8192;
#pragma unroll
            for (int ks = 0; ks < 4; ++ks) {
                uint32_t ahi[4], alo[4], bhi[4][2], blo[4][2];
                int ac = (2 * ks + a_kh) ^ (a_r15 & 7);
                uint32_t aoff = (uint32_t)((wm * 16 + a_r15) * 128 + ac * 16);
                LDM_X4(ahi[0], ahi[1], ahi[2], ahi[3], aHiB + aoff);
                LDM_X4(alo[0], alo[1], alo[2], alo[3], aLoB + aoff);
#pragma unroll
                for (int tn2 = 0; tn2 < 2; ++tn2) {
                    int row = wn * 32 + tn2 * 16 + b_row;
                    int bc = (2 * ks + b_kh) ^ (b_row & 7);
                    uint32_t boff = (uint32_t)(row * 128 + bc * 16);
                    uint32_t r0, r1, r2, r3;
                    LDM_X4(r0, r1, r2, r3, bHiB + boff);
                    bhi[tn2 * 2 + 0][0] = r0; bhi[tn2 * 2 + 0][1] = r1;
                    bhi[tn2 * 2 + 1][0] = r2; bhi[tn2 * 2 + 1][1] = r3;
                    LDM_X4(r0, r1, r2, r3, bLoB + boff);
                    blo[tn2 * 2 + 0][0] = r0; blo[tn2 * 2 + 0][1] = r1;
                    blo[tn2 * 2 + 1][0] = r2; blo[tn2 * 2 + 1][1] = r3;
                }
#pragma unroll
                for (int tn = 0; tn < 4; ++tn) MMA16816(cfr[tn], ahi, bhi[tn]);
#pragma unroll
                for (int tn = 0; tn < 4; ++tn) MMA16816(cfr[tn], alo, bhi[tn]);
#pragma unroll
                for (int tn = 0; tn < 4; ++tn) MMA16816(cfr[tn], ahi, blo[tn]);
            }
        }

        // scatter c-frags to gate bounce buffer
        int qr = lane >> 2, qc = (lane & 3) * 2;
#pragma unroll
        for (int tn = 0; tn < 4; ++tn) {
            int col = wn * 32 + tn * 8 + qc;
            int r0 = wm * 16 + qr;
            *(float2*)&gbuf[r0 * 68 + col] = make_float2(cfr[tn][0], cfr[tn][1]);
            *(float2*)&gbuf[(r0 + 8) * 68 + col] = make_float2(cfr[tn][2], cfr[tn][3]);
        }
        __syncthreads();

        // LSTM epilogue: thread reads 16 contiguous gates (4 hid x 4 q)
        float ga[16];
#pragma unroll
        for (int j4 = 0; j4 < 4; ++j4) {
            float4 v = *(const float4*)&gbuf[eb * 68 + eh4 * 16 + j4 * 4];
            ga[j4 * 4 + 0] = v.x; ga[j4 * 4 + 1] = v.y;
            ga[j4 * 4 + 2] = v.z; ga[j4 * 4 + 3] = v.w;
        }
        float hn[4];
#pragma unroll
        for (int j = 0; j < 4; ++j) {
            float gi = ga[j * 4 + 0] + g1s[0 * 4 + j];
            float gf = ga[j * 4 + 1] + g1s[1 * 4 + j];
            float gg = ga[j * 4 + 2] + g1s[2 * 4 + j];
            float go = ga[j * 4 + 3] + g1s[3 * 4 + j];
            float cc = fmaf(sigf(gf), creg[j], sigf(gi) * tanhfast(gg));
            creg[j] = cc;
            hn[j] = sigf(go) * tanhfast(cc);
        }
        // producer-side bf16 hi/lo split (replaces consumer-side per-step split)
        float4 hv = make_float4(hn[0], hn[1], hn[2], hn[3]);
        uint2 hiv, lov;
        split4(hv, hiv, lov);
        size_t hoff = (size_t)(b0 + eb) * H_ + h0 + eh4 * 4;
        __stcg((uint2*)(g_hbf[(t + 1) & 1][0] + hoff), hiv);
        __stcg((uint2*)(g_hbf[(t + 1) & 1][1] + hoff), lov);
        *(float4*)(out_enc + ((size_t)(b0 + eb) * T_ + t) * H_ + h0 + eh4 * 4) = hv;

        if (t + 1 < T_) {
            // prefetch G1 for t+1 (loads fly during barrier)
#pragma unroll
            for (int q = 0; q < 4; ++q) {
                float4 v = __ldcg((const float4*)(g_G1 + ((size_t)(t + 1) * B_ + b0 + eb) * G_ + q * 256 + h0 + eh4 * 4));
                g1s[q * 4 + 0] = v.x; g1s[q * 4 + 1] = v.y;
                g1s[q * 4 + 2] = v.z; g1s[q * 4 + 3] = v.w;
            }
            // ---- group barrier (16 CTAs, monotonic counter — proven R11) ----
            __threadfence();
            __syncthreads();
            if (tid == 0) atomicAdd(&g_cnt_grp[grp * 32], 1u);
            unsigned target = (unsigned)(t + 1) * 16u;
            volatile unsigned* cp = &g_cnt_grp[grp * 32];
            while (*cp < target) { __nanosleep(32); }
            __threadfence();
        }
    }
}

// ---------------- launch ----------------
extern "C" void kernel_launch(void* const* d_in, const int* in_sizes, int n_in,
                              void* d_out, int out_size) {
    const float* input  = (const float*)d_in[0];
    const float* W_ih   = (const float*)d_in[1];
    const float* W_hh   = (const float*)d_in[2];
    const float* b_ih   = (const float*)d_in[3];
    const float* b_hh   = (const float*)d_in[4];
    const float* attn_w = (const float*)d_in[5];
    float* out = (float*)d_out;

    cudaFuncSetAttribute(k_recur, cudaFuncAttributeMaxDynamicSharedMemorySize, S_TOT);

    // K1: attention weights (+ zero h planes, zero group counters)
    k_attn<<<B_, N_>>>(input, attn_w);
    // K2: weighted input -> output region 0 + bf16 hi/lo staging
    k_weighted<<<B_ * T_, N_>>>(input, out);
    // K2b: W_ih bf16 hi/lo
    k_convB<<<G_, N_>>>(W_ih);
    // K3: HMMA split-bf16 GEMM into g_G1, cp.async double-buffered
    dim3 g3(8, 1024);
    k_gemm_mma<<<g3, 256>>>(b_ih, b_hh);
    // K4: persistent recurrence -> output region 1 (cp.async h staging)
    dim3 g4(8, 16);
    k_recur<<<g4, 128, S_TOT>>>(W_hh, out + ENC_OFF);
}

// round 15
// speedup vs baseline: 1.1903x; 1.0106x over previous
#include <cuda_runtime.h>
#include <cuda_bf16.h>
#include <cstdint>

// Problem constants
#define B_ 256
#define T_ 512          // TM1
#define N_ 256
#define H_ 256
#define G_ 1024         // 4*H
#define ENC_OFF ((size_t)B_ * T_ * N_)   // offset of input_encoded in d_out

// ---------------- device scratch (no cudaMalloc allowed) ----------------
__device__ float g_attn[B_ * N_];                      // softmax(x_scores)
__device__ float g_G1[(size_t)T_ * B_ * G_];           // gates pre-recurrence, [m=t*B+b][j]
__device__ __nv_bfloat16 g_hbf[2][2][B_ * H_];         // h ping-pong x {hi,lo} planes, [b][h]
__device__ __nv_bfloat16 g_Ahi[(size_t)T_ * B_ * N_];  // weighted, bf16 hi
__device__ __nv_bfloat16 g_Alo[(size_t)T_ * B_ * N_];  // weighted, bf16 lo
__device__ __nv_bfloat16 g_Bhi[G_ * N_];               // W_ih, bf16 hi
__device__ __nv_bfloat16 g_Blo[G_ * N_];               // W_ih, bf16 lo
// Group barrier: MONOTONIC counters (never reset -> no lost-arrival race),
// 128B padded per group, zeroed by k_attn at the start of every launch.
__device__ unsigned g_cnt_grp[256];

// ---------------- helpers ----------------
__device__ __forceinline__ float sigf(float x) {
    return __fdividef(1.f, 1.f + __expf(-x));
}
__device__ __forceinline__ float tanhfast(float x) {
    return __fdividef(2.f, 1.f + __expf(-2.f * x)) - 1.f;
}
__device__ __forceinline__ uint32_t smem_to_u32(const void* p) {
    uint32_t a;
    asm("{ .reg .u64 t; cvta.to.shared.u64 t, %1; cvt.u32.u64 %0, t; }" : "=r"(a) : "l"(p));
    return a;
}
__device__ __forceinline__ void split4(float4 v, uint2& hi, uint2& lo) {
    __nv_bfloat16 hx = __float2bfloat16(v.x);
    __nv_bfloat16 hy = __float2bfloat16(v.y);
    __nv_bfloat16 hz = __float2bfloat16(v.z);
    __nv_bfloat16 hw = __float2bfloat16(v.w);
    __nv_bfloat16 lx = __float2bfloat16(v.x - __bfloat162float(hx));
    __nv_bfloat16 ly = __float2bfloat16(v.y - __bfloat162float(hy));
    __nv_bfloat16 lz = __float2bfloat16(v.z - __bfloat162float(hz));
    __nv_bfloat16 lw = __float2bfloat16(v.w - __bfloat162float(hw));
    __nv_bfloat162 h01(hx, hy), h23(hz, hw), l01(lx, ly), l23(lz, lw);
    hi.x = *reinterpret_cast<uint32_t*>(&h01);
    hi.y = *reinterpret_cast<uint32_t*>(&h23);
    lo.x = *reinterpret_cast<uint32_t*>(&l01);
    lo.y = *reinterpret_cast<uint32_t*>(&l23);
}

// ---------------- cp.async helpers ----------------
#define CP_ASYNC16(dst, src) \
    asm volatile("cp.async.cg.shared.global [%0], [%1], 16;" :: "r"(dst), "l"(src) : "memory")
#define CP_COMMIT() asm volatile("cp.async.commit_group;" ::: "memory")
#define CP_WAITN(n) asm volatile("cp.async.wait_group %0;" :: "n"(n) : "memory")
#define CP_WAIT1() asm volatile("cp.async.wait_group 1;" ::: "memory")
#define CP_WAIT0() asm volatile("cp.async.wait_group 0;" ::: "memory")

// ---------------- mma helpers (proven in K3) ----------------
#define LDM_X4(r0, r1, r2, r3, a) \
    asm volatile("ldmatrix.sync.aligned.m8n8.x4.shared.b16 {%0,%1,%2,%3}, [%4];" \
                 : "=r"(r0), "=r"(r1), "=r"(r2), "=r"(r3) : "r"(a))
#define MMA16816(c, a, b) \
    asm volatile("mma.sync.aligned.m16n8k16.row.col.f32.bf16.bf16.f32 " \
                 "{%0,%1,%2,%3}, {%4,%5,%6,%7}, {%8,%9}, {%0,%1,%2,%3};" \
                 : "+f"((c)[0]), "+f"((c)[1]), "+f"((c)[2]), "+f"((c)[3]) \
                 : "r"((a)[0]), "r"((a)[1]), "r"((a)[2]), "r"((a)[3]), "r"((b)[0]), "r"((b)[1]))

// ---------------- K1: x_scores + softmax -> attn, zero h planes + counters ----
__global__ void k_attn(const float* __restrict__ in, const float* __restrict__ attn_w) {
    __shared__ float wx[T_];
    __shared__ float red[N_];
    int b = blockIdx.x;
    int n = threadIdx.x;

    if (b == 0) g_cnt_grp[n] = 0;    // reset group-barrier counters every launch

    wx[n]       = attn_w[2 * H_ + n];
    wx[n + 256] = attn_w[2 * H_ + 256 + n];
    __syncthreads();

    const float* p = in + (size_t)b * T_ * N_ + n;
    float acc = 0.f;
#pragma unroll 8
    for (int t = 0; t < T_; ++t)
        acc = fmaf(p[(size_t)t * N_], wx[t], acc);

    red[n] = acc;
    __syncthreads();
    for (int s = 128; s > 0; s >>= 1) {
        if (n < s) red[n] = fmaxf(red[n], red[n + s]);
        __syncthreads();
    }
    float mx = red[0];
    __syncthreads();
    float e = expf(acc - mx);
    red[n] = e;
    __syncthreads();
    for (int s = 128; s > 0; s >>= 1) {
        if (n < s) red[n] += red[n + s];
        __syncthreads();
    }
    g_attn[b * N_ + n] = e / red[0];
    // zero initial hidden-state bf16 planes
    g_hbf[0][0][b * N_ + n] = __float2bfloat16(0.f);
    g_hbf[0][1][b * N_ + n] = __float2bfloat16(0.f);
}

// ---------------- K2: weighted = attn * x -> out region 0 + bf16 hi/lo ---------
__global__ void k_weighted(const float* __restrict__ in, float* __restrict__ out) {
    int blk = blockIdx.x;            // b*T_ + t
    int b = blk >> 9;
    int t = blk & 511;
    int n = threadIdx.x;
    size_t idx = (size_t)blk * N_ + n;
    float w = g_attn[b * N_ + n] * in[idx];
    out[idx] = w;
    size_t m = (size_t)t * B_ + b;   // GEMM row index
    __nv_bfloat16 hi = __float2bfloat16(w);
    __nv_bfloat16 lo = __float2bfloat16(w - __bfloat162float(hi));
    g_Ahi[m * N_ + n] = hi;
    g_Alo[m * N_ + n] = lo;
}

// ---------------- K2b: W_ih -> bf16 hi/lo ----------------
__global__ void k_convB(const float* __restrict__ Wih) {
    int j = blockIdx.x;
    int k = threadIdx.x;
    float v = Wih[(size_t)j * N_ + k];
    __nv_bfloat16 hi = __float2bfloat16(v);
    __nv_bfloat16 lo = __float2bfloat16(v - __bfloat162float(hi));
    g_Bhi[j * N_ + k] = hi;
    g_Blo[j * N_ + k] = lo;
}

// ---------------- K3: mma.sync bf16 split GEMM, cp.async double-buffered -------
// (unchanged — proven at 517us)
#define TILE_BYTES 16384           // 128 x 64 bf16

__global__ void __launch_bounds__(256) k_gemm_mma(
        const float* __restrict__ b_ih, const float* __restrict__ b_hh) {
    __shared__ __align__(16) __nv_bfloat16 Sb[4 * 128 * 64];   // 64 KB
    __shared__ float bias_s[128];

    int tid = threadIdx.x;
    int wid = tid >> 5;
    int lane = tid & 31;
    int nt = blockIdx.x;             // 0..7  gate tile
    int mt = blockIdx.y;             // 0..1023 m tile
    int j0 = nt * 128;
    int wm = wid >> 2;               // 0..1
    int wn = wid & 3;                // 0..3

    if (tid < 128) bias_s[tid] = b_ih[j0 + tid] + b_hh[j0 + tid];

    uint32_t s_base = smem_to_u32(Sb);

    int st_r[4], st_sw[4];
#pragma unroll
    for (int it = 0; it < 4; ++it) {
        int idx = tid + it * 256;        // 0..1023
        int r = idx >> 3;
        int kg = idx & 7;
        st_r[it] = r * 32 + kg;
        st_sw[it] = r * 8 + (kg ^ (r & 7));
    }

    const __nv_bfloat16* a_srcs[3] = {g_Ahi, g_Alo, g_Ahi};
    const __nv_bfloat16* b_srcs[3] = {g_Bhi, g_Bhi, g_Blo};

#define ISSUE_CHUNK(ch) do { \
        int _term = (ch) >> 2; \
        int _kk0 = ((ch) & 3) * 64; \
        const char* _gA = (const char*)(a_srcs[_term] + (size_t)mt * 128 * N_ + _kk0); \
        const char* _gB = (const char*)(b_srcs[_term] + (size_t)j0 * N_ + _kk0); \
        uint32_t _sa = s_base + ((ch) & 1) * 2u * TILE_BYTES; \
        uint32_t _sb = _sa + TILE_BYTES; \
        _Pragma("unroll") \
        for (int _it = 0; _it < 4; ++_it) { \
            CP_ASYNC16(_sa + (uint32_t)st_sw[_it] * 16u, _gA + (size_t)st_r[_it] * 16); \
            CP_ASYNC16(_sb + (uint32_t)st_sw[_it] * 16u, _gB + (size_t)st_r[_it] * 16); \
        } \
        CP_COMMIT(); \
    } while (0)

    int a_r15 = lane & 15;
    int a_kh  = lane >> 4;
    int b_row = ((lane & 16) >> 1) + (lane & 7);
    int b_kh  = (lane >> 3) & 1;

    float acc[4][4][4];
#pragma unroll
    for (int i = 0; i < 4; ++i)
#pragma unroll
        for (int j = 0; j < 4; ++j)
#pragma unroll
            for (int q = 0; q < 4; ++q) acc[i][j][q] = 0.f;

    ISSUE_CHUNK(0);

    for (int ch = 0; ch < 12; ++ch) {
        if (ch + 1 < 12) {
            ISSUE_CHUNK(ch + 1);
            CP_WAIT1();
        } else {
            CP_WAIT0();
        }
        __syncthreads();

        uint32_t as_base = s_base + (ch & 1) * 2u * TILE_BYTES;
        uint32_t bs_base = as_base + TILE_BYTES;

#pragma unroll
        for (int ks = 0; ks < 4; ++ks) {
            uint32_t afr[4][4];
            uint32_t bfr[4][2];
#pragma unroll
            for (int tm = 0; tm < 4; ++tm) {
                int row = wm * 64 + tm * 16 + a_r15;
                int c = (2 * ks + a_kh) ^ (a_r15 & 7);
                uint32_t addr = as_base + (uint32_t)(row * 64 + c * 8) * 2u;
                LDM_X4(afr[tm][0], afr[tm][1], afr[tm][2], afr[tm][3], addr);
            }
#pragma unroll
            for (int tn2 = 0; tn2 < 2; ++tn2) {
                int row = wn * 32 + tn2 * 16 + b_row;
                int c = (2 * ks + b_kh) ^ (b_row & 7);
                uint32_t addr = bs_base + (uint32_t)(row * 64 + c * 8) * 2u;
                uint32_t r0, r1, r2, r3;
                LDM_X4(r0, r1, r2, r3, addr);
                bfr[tn2 * 2 + 0][0] = r0; bfr[tn2 * 2 + 0][1] = r1;
                bfr[tn2 * 2 + 1][0] = r2; bfr[tn2 * 2 + 1][1] = r3;
            }
#pragma unroll
            for (int tm = 0; tm < 4; ++tm)
#pragma unroll
                for (int tn = 0; tn < 4; ++tn)
                    MMA16816(acc[tm][tn], afr[tm], bfr[tn]);
        }
        __syncthreads();
    }

    int qr = lane >> 2;
    int qc = (lane & 3) * 2;
#pragma unroll
    for (int tm = 0; tm < 4; ++tm) {
#pragma unroll
        for (int tn = 0; tn < 4; ++tn) {
            int colt = wn * 32 + tn * 8 + qc;
            size_t m0 = (size_t)mt * 128 + wm * 64 + tm * 16 + qr;
            float bx = bias_s[colt], by = bias_s[colt + 1];
            float2 v0 = make_float2(acc[tm][tn][0] + bx, acc[tm][tn][1] + by);
            float2 v1 = make_float2(acc[tm][tn][2] + bx, acc[tm][tn][3] + by);
            *(float2*)(g_G1 + m0 * G_ + j0 + colt) = v0;
            *(float2*)(g_G1 + (m0 + 8) * G_ + j0 + colt) = v1;
        }
    }
}

// ---------------- K4: persistent recurrence, tensor-core inner GEMM ------------
// R14 structure (128 threads, proven 2944us) with two micro-opts:
//  (a) kc-pipelined staging: 4 cp.async commit groups (one per kc chunk);
//      mma on kc waits only for chunks <= kc -> later chunks' latency hides
//      behind earlier chunks' mma.
//  (b) early barrier arrival: arrive right after h stores are fenced; out_enc
//      store + G1 prefetch execute inside the peers' arrival window.
#define S_WHI 0
#define S_WLO 32768
#define S_AHI 65536
#define S_ALO 81920
#define S_GB  98304
#define S_TOT 107008

__global__ void __launch_bounds__(128, 1) k_recur(
        const float* __restrict__ Whh, float* __restrict__ out_enc) {
    extern __shared__ __align__(16) char smem[];
    uint32_t s_base = smem_to_u32(smem);
    float* gbuf = (float*)(smem + S_GB);      // [32][68] fp32 gate bounce

    int tid = threadIdx.x;            // 128 = 4 warps
    int lane = tid & 31;
    int wid = tid >> 5;
    int wm = wid & 1;                 // m half (16 batches)
    int wn = wid >> 1;                // n half (32 gate cols)
    int b0 = blockIdx.x * 32;
    int h0 = blockIdx.y * 16;
    int grp = blockIdx.x;

    // Build W bf16 hi/lo subtiles once (layout proven R12).
    for (int idx = tid; idx < 4096; idx += 128) {
        int n = idx >> 6;             // 0..63
        int kq = idx & 63;            // float4 index along k
        int hid = n >> 2, q = n & 3;
        float4 v = *(const float4*)(Whh + (size_t)(q * H_ + h0 + hid) * N_ + kq * 4);
        uint2 hi, lo;
        split4(v, hi, lo);
        int kc = kq >> 4, kk = kq & 15, kg = kk >> 1, half = kk & 1;
        uint32_t off = (uint32_t)(kc * 8192 + n * 128 + ((kg ^ (n & 7)) << 4) + half * 8);
        *(uint2*)(smem + S_WHI + off) = hi;
        *(uint2*)(smem + S_WLO + off) = lo;
    }

    // ldmatrix lane precompute (identical to K3)
    int a_r15 = lane & 15;
    int a_kh  = lane >> 4;
    int b_row = ((lane & 16) >> 1) + (lane & 7);
    int b_kh  = (lane >> 3) & 1;

    // kc-ordered staging indices: per kc, 256 granules; thread covers 2 per plane.
    int stg_b[4][2], stg_kg[4][2];
#pragma unroll
    for (int kc = 0; kc < 4; ++kc)
#pragma unroll
        for (int sub = 0; sub < 2; ++sub) {
            int idx = sub * 128 + tid;    // 0..255 within chunk
            stg_b[kc][sub] = idx >> 3;
            stg_kg[kc][sub] = idx & 7;
        }

    // epilogue mapping: thread owns batch eb, hids [eh4*4, eh4*4+4)
    int eb  = tid & 31;
    int eh4 = tid >> 5;

    float creg[4] = {0.f, 0.f, 0.f, 0.f};
    __syncthreads();

    // G1 prefetch for t=0: g1s[q*4+j]
    float g1s[16];
#pragma unroll
    for (int q = 0; q < 4; ++q) {
        float4 v = __ldcg((const float4*)(g_G1 + ((size_t)(b0 + eb)) * G_ + q * 256 + h0 + eh4 * 4));
        g1s[q * 4 + 0] = v.x; g1s[q * 4 + 1] = v.y;
        g1s[q * 4 + 2] = v.z; g1s[q * 4 + 3] = v.w;
    }

    for (int t = 0; t < T_; ++t) {
        // stage h bf16 planes -> swizzled A subtiles, one commit group PER kc
        const char* srcHi = (const char*)(g_hbf[t & 1][0] + (size_t)b0 * H_);
        const char* srcLo = (const char*)(g_hbf[t & 1][1] + (size_t)b0 * H_);
#pragma unroll
        for (int kc = 0; kc < 4; ++kc) {
#pragma unroll
            for (int sub = 0; sub < 2; ++sub) {
                int b = stg_b[kc][sub], kg = stg_kg[kc][sub];
                uint32_t doff = (uint32_t)(kc * 4096 + b * 128 + ((kg ^ (b & 7)) << 4));
                size_t soff = (size_t)b * 512 + kc * 128 + kg * 16;
                CP_ASYNC16(s_base + S_AHI + doff, srcHi + soff);
                CP_ASYNC16(s_base + S_ALO + doff, srcLo + soff);
            }
            CP_COMMIT();
        }

        // D = h @ W^T, 3-term bf16 split; per-kc pipelined wait
        float cfr[4][4];
#pragma unroll
        for (int tn = 0; tn < 4; ++tn)
#pragma unroll
            for (int q = 0; q < 4; ++q) cfr[tn][q] = 0.f;

#pragma unroll
        for (int kc = 0; kc < 4; ++kc) {
            if (kc == 0)      CP_WAITN(3);
            else if (kc == 1) CP_WAITN(2);
            else if (kc == 2) CP_WAITN(1);
            else              CP_WAITN(0);
            __syncthreads();

            uint32_t aHiB = s_base + S_AHI + kc * 4096;
            uint32_t aLoB = s_base + S_ALO + kc * 4096;
            uint32_t bHiB = s_base + S_WHI + kc * 8192;
            uint32_t bLoB = s_base + S_WLO + kc * 8192;
#pragma unroll
            for (int ks = 0; ks < 4; ++ks) {
                uint32_t ahi[4], alo[4], bhi[4][2], blo[4][2];
                int ac = (2 * ks + a_kh) ^ (a_r15 & 7);
                uint32_t aoff = (uint32_t)((wm * 16 + a_r15) * 128 + ac * 16);
                LDM_X4(ahi[0], ahi[1], ahi[2], ahi[3], aHiB + aoff);
                LDM_X4(alo[0], alo[1], alo[2], alo[3], aLoB + aoff);
#pragma unroll
                for (int tn2 = 0; tn2 < 2; ++tn2) {
                    int row = wn * 32 + tn2 * 16 + b_row;
                    int bc = (2 * ks + b_kh) ^ (b_row & 7);
                    uint32_t boff = (uint32_t)(row * 128 + bc * 16);
                    uint32_t r0, r1, r2, r3;
                    LDM_X4(r0, r1, r2, r3, bHiB + boff);
                    bhi[tn2 * 2 + 0][0] = r0; bhi[tn2 * 2 + 0][1] = r1;
                    bhi[tn2 * 2 + 1][0] = r2; bhi[tn2 * 2 + 1][1] = r3;
                    LDM_X4(r0, r1, r2, r3, bLoB + boff);
                    blo[tn2 * 2 + 0][0] = r0; blo[tn2 * 2 + 0][1] = r1;
                    blo[tn2 * 2 + 1][0] = r2; blo[tn2 * 2 + 1][1] = r3;
                }
#pragma unroll
                for (int tn = 0; tn < 4; ++tn) MMA16816(cfr[tn], ahi, bhi[tn]);
#pragma unroll
                for (int tn = 0; tn < 4; ++tn) MMA16816(cfr[tn], alo, bhi[tn]);
#pragma unroll
                for (int tn = 0; tn < 4; ++tn) MMA16816(cfr[tn], ahi, blo[tn]);
            }
        }

        // scatter c-frags to gate bounce buffer
        int qr = lane >> 2, qc = (lane & 3) * 2;
#pragma unroll
        for (int tn = 0; tn < 4; ++tn) {
            int col = wn * 32 + tn * 8 + qc;
            int r0 = wm * 16 + qr;
            *(float2*)&gbuf[r0 * 68 + col] = make_float2(cfr[tn][0], cfr[tn][1]);
            *(float2*)&gbuf[(r0 + 8) * 68 + col] = make_float2(cfr[tn][2], cfr[tn][3]);
        }
        __syncthreads();

        // LSTM epilogue: thread reads 16 contiguous gates (4 hid x 4 q)
        float ga[16];
#pragma unroll
        for (int j4 = 0; j4 < 4; ++j4) {
            float4 v = *(const float4*)&gbuf[eb * 68 + eh4 * 16 + j4 * 4];
            ga[j4 * 4 + 0] = v.x; ga[j4 * 4 + 1] = v.y;
            ga[j4 * 4 + 2] = v.z; ga[j4 * 4 + 3] = v.w;
        }
        float hn[4];
#pragma unroll
        for (int j = 0; j < 4; ++j) {
            float gi = ga[j * 4 + 0] + g1s[0 * 4 + j];
            float gf = ga[j * 4 + 1] + g1s[1 * 4 + j];
            float gg = ga[j * 4 + 2] + g1s[2 * 4 + j];
            float go = ga[j * 4 + 3] + g1s[3 * 4 + j];
            float cc = fmaf(sigf(gf), creg[j], sigf(gi) * tanhfast(gg));
            creg[j] = cc;
            hn[j] = sigf(go) * tanhfast(cc);
        }
        // producer-side bf16 hi/lo split; h stores FIRST (peers wait on these)
        float4 hv = make_float4(hn[0], hn[1], hn[2], hn[3]);
        uint2 hiv, lov;
        split4(hv, hiv, lov);
        size_t hoff = (size_t)(b0 + eb) * H_ + h0 + eh4 * 4;
        __stcg((uint2*)(g_hbf[(t + 1) & 1][0] + hoff), hiv);
        __stcg((uint2*)(g_hbf[(t + 1) & 1][1] + hoff), lov);

        if (t + 1 < T_) {
            // ---- EARLY arrival: release h stores, signal, then fill the wait
            //      window with the out_enc store + G1 prefetch ----
            __threadfence();
            __syncthreads();
            if (tid == 0) atomicAdd(&g_cnt_grp[grp * 32], 1u);

            *(float4*)(out_enc + ((size_t)(b0 + eb) * T_ + t) * H_ + h0 + eh4 * 4) = hv;
#pragma unroll
            for (int q = 0; q < 4; ++q) {
                float4 v = __ldcg((const float4*)(g_G1 + ((size_t)(t + 1) * B_ + b0 + eb) * G_ + q * 256 + h0 + eh4 * 4));
                g1s[q * 4 + 0] = v.x; g1s[q * 4 + 1] = v.y;
                g1s[q * 4 + 2] = v.z; g1s[q * 4 + 3] = v.w;
            }

            unsigned target = (unsigned)(t + 1) * 16u;
            volatile unsigned* cp = &g_cnt_grp[grp * 32];
            while (*cp < target) { __nanosleep(32); }
            __threadfence();
        } else {
            *(float4*)(out_enc + ((size_t)(b0 + eb) * T_ + t) * H_ + h0 + eh4 * 4) = hv;
        }
    }
}

// ---------------- launch ----------------
extern "C" void kernel_launch(void* const* d_in, const int* in_sizes, int n_in,
                              void* d_out, int out_size) {
    const float* input  = (const float*)d_in[0];
    const float* W_ih   = (const float*)d_in[1];
    const float* W_hh   = (const float*)d_in[2];
    const float* b_ih   = (const float*)d_in[3];
    const float* b_hh   = (const float*)d_in[4];
    const float* attn_w = (const float*)d_in[5];
    float* out = (float*)d_out;

    cudaFuncSetAttribute(k_recur, cudaFuncAttributeMaxDynamicSharedMemorySize, S_TOT);

    // K1: attention weights (+ zero h planes, zero group counters)
    k_attn<<<B_, N_>>>(input, attn_w);
    // K2: weighted input -> output region 0 + bf16 hi/lo staging
    k_weighted<<<B_ * T_, N_>>>(input, out);
    // K2b: W_ih bf16 hi/lo
    k_convB<<<G_, N_>>>(W_ih);
    // K3: HMMA split-bf16 GEMM into g_G1, cp.async double-buffered
    dim3 g3(8, 1024);
    k_gemm_mma<<<g3, 256>>>(b_ih, b_hh);
    // K4: persistent recurrence -> output region 1 (pipelined staging, early arrive)
    dim3 g4(8, 16);
    k_recur<<<g4, 128, S_TOT>>>(W_hh, out + ENC_OFF);
}

// round 16
// speedup vs baseline: 1.1931x; 1.0023x over previous
#include <cuda_runtime.h>
#include <cuda_bf16.h>
#include <cstdint>

// Problem constants
#define B_ 256
#define T_ 512          // TM1
#define N_ 256
#define H_ 256
#define G_ 1024         // 4*H
#define ENC_OFF ((size_t)B_ * T_ * N_)   // offset of input_encoded in d_out

// ---------------- device scratch (no cudaMalloc allowed) ----------------
__device__ float g_attn[B_ * N_];                      // softmax(x_scores)
__device__ float g_G1[(size_t)T_ * B_ * G_];           // gates pre-recurrence, [m=t*B+b][j]
__device__ __nv_bfloat16 g_hbf[2][2][B_ * H_];         // h ping-pong x {hi,lo} planes, [b][h]
__device__ __nv_bfloat16 g_Ahi[(size_t)T_ * B_ * N_];  // weighted, bf16 hi
__device__ __nv_bfloat16 g_Alo[(size_t)T_ * B_ * N_];  // weighted, bf16 lo
__device__ __nv_bfloat16 g_Bhi[G_ * N_];               // W_ih, bf16 hi
__device__ __nv_bfloat16 g_Blo[G_ * N_];               // W_ih, bf16 lo
// Group barrier: MONOTONIC counters (never reset -> no lost-arrival race),
// 128B padded per group, zeroed by k_attn at the start of every launch.
__device__ unsigned g_cnt_grp[256];

// ---------------- helpers ----------------
__device__ __forceinline__ float sigf(float x) {
    return __fdividef(1.f, 1.f + __expf(-x));
}
__device__ __forceinline__ float tanhfast(float x) {
    return __fdividef(2.f, 1.f + __expf(-2.f * x)) - 1.f;
}
__device__ __forceinline__ uint32_t smem_to_u32(const void* p) {
    uint32_t a;
    asm("{ .reg .u64 t; cvta.to.shared.u64 t, %1; cvt.u32.u64 %0, t; }" : "=r"(a) : "l"(p));
    return a;
}
__device__ __forceinline__ void split4(float4 v, uint2& hi, uint2& lo) {
    __nv_bfloat16 hx = __float2bfloat16(v.x);
    __nv_bfloat16 hy = __float2bfloat16(v.y);
    __nv_bfloat16 hz = __float2bfloat16(v.z);
    __nv_bfloat16 hw = __float2bfloat16(v.w);
    __nv_bfloat16 lx = __float2bfloat16(v.x - __bfloat162float(hx));
    __nv_bfloat16 ly = __float2bfloat16(v.y - __bfloat162float(hy));
    __nv_bfloat16 lz = __float2bfloat16(v.z - __bfloat162float(hz));
    __nv_bfloat16 lw = __float2bfloat16(v.w - __bfloat162float(hw));
    __nv_bfloat162 h01(hx, hy), h23(hz, hw), l01(lx, ly), l23(lz, lw);
    hi.x = *reinterpret_cast<uint32_t*>(&h01);
    hi.y = *reinterpret_cast<uint32_t*>(&h23);
    lo.x = *reinterpret_cast<uint32_t*>(&l01);
    lo.y = *reinterpret_cast<uint32_t*>(&l23);
}

// ---------------- cp.async helpers ----------------
#define CP_ASYNC16(dst, src) \
    asm volatile("cp.async.cg.shared.global [%0], [%1], 16;" :: "r"(dst), "l"(src) : "memory")
#define CP_COMMIT() asm volatile("cp.async.commit_group;" ::: "memory")
#define CP_WAITN(n) asm volatile("cp.async.wait_group %0;" :: "n"(n) : "memory")
#define CP_WAIT1() asm volatile("cp.async.wait_group 1;" ::: "memory")
#define CP_WAIT0() asm volatile("cp.async.wait_group 0;" ::: "memory")

// ---------------- mma helpers (proven in K3) ----------------
#define LDM_X4(r0, r1, r2, r3, a) \
    asm volatile("ldmatrix.sync.aligned.m8n8.x4.shared.b16 {%0,%1,%2,%3}, [%4];" \
                 : "=r"(r0), "=r"(r1), "=r"(r2), "=r"(r3) : "r"(a))
#define MMA16816(c, a, b) \
    asm volatile("mma.sync.aligned.m16n8k16.row.col.f32.bf16.bf16.f32 " \
                 "{%0,%1,%2,%3}, {%4,%5,%6,%7}, {%8,%9}, {%0,%1,%2,%3};" \
                 : "+f"((c)[0]), "+f"((c)[1]), "+f"((c)[2]), "+f"((c)[3]) \
                 : "r"((a)[0]), "r"((a)[1]), "r"((a)[2]), "r"((a)[3]), "r"((b)[0]), "r"((b)[1]))

// ---------------- K1: x_scores + softmax -> attn, zero h planes + counters ----
__global__ void k_attn(const float* __restrict__ in, const float* __restrict__ attn_w) {
    __shared__ float wx[T_];
    __shared__ float red[N_];
    int b = blockIdx.x;
    int n = threadIdx.x;

    if (b == 0) g_cnt_grp[n] = 0;    // reset group-barrier counters every launch

    wx[n]       = attn_w[2 * H_ + n];
    wx[n + 256] = attn_w[2 * H_ + 256 + n];
    __syncthreads();

    const float* p = in + (size_t)b * T_ * N_ + n;
    float acc = 0.f;
#pragma unroll 8
    for (int t = 0; t < T_; ++t)
        acc = fmaf(p[(size_t)t * N_], wx[t], acc);

    red[n] = acc;
    __syncthreads();
    for (int s = 128; s > 0; s >>= 1) {
        if (n < s) red[n] = fmaxf(red[n], red[n + s]);
        __syncthreads();
    }
    float mx = red[0];
    __syncthreads();
    float e = expf(acc - mx);
    red[n] = e;
    __syncthreads();
    for (int s = 128; s > 0; s >>= 1) {
        if (n < s) red[n] += red[n + s];
        __syncthreads();
    }
    g_attn[b * N_ + n] = e / red[0];
    // zero initial hidden-state bf16 planes
    g_hbf[0][0][b * N_ + n] = __float2bfloat16(0.f);
    g_hbf[0][1][b * N_ + n] = __float2bfloat16(0.f);
}

// ---------------- K2: weighted = attn * x -> out region 0 + bf16 hi/lo ---------
__global__ void k_weighted(const float* __restrict__ in, float* __restrict__ out) {
    int blk = blockIdx.x;            // b*T_ + t
    int b = blk >> 9;
    int t = blk & 511;
    int n = threadIdx.x;
    size_t idx = (size_t)blk * N_ + n;
    float w = g_attn[b * N_ + n] * in[idx];
    out[idx] = w;
    size_t m = (size_t)t * B_ + b;   // GEMM row index
    __nv_bfloat16 hi = __float2bfloat16(w);
    __nv_bfloat16 lo = __float2bfloat16(w - __bfloat162float(hi));
    g_Ahi[m * N_ + n] = hi;
    g_Alo[m * N_ + n] = lo;
}

// ---------------- K2b: W_ih -> bf16 hi/lo ----------------
__global__ void k_convB(const float* __restrict__ Wih) {
    int j = blockIdx.x;
    int k = threadIdx.x;
    float v = Wih[(size_t)j * N_ + k];
    __nv_bfloat16 hi = __float2bfloat16(v);
    __nv_bfloat16 lo = __float2bfloat16(v - __bfloat162float(hi));
    g_Bhi[j * N_ + k] = hi;
    g_Blo[j * N_ + k] = lo;
}

// ---------------- K3: mma.sync bf16 split GEMM, cp.async double-buffered -------
// (unchanged — proven at 517us)
#define TILE_BYTES 16384           // 128 x 64 bf16

__global__ void __launch_bounds__(256) k_gemm_mma(
        const float* __restrict__ b_ih, const float* __restrict__ b_hh) {
    __shared__ __align__(16) __nv_bfloat16 Sb[4 * 128 * 64];   // 64 KB
    __shared__ float bias_s[128];

    int tid = threadIdx.x;
    int wid = tid >> 5;
    int lane = tid & 31;
    int nt = blockIdx.x;             // 0..7  gate tile
    int mt = blockIdx.y;             // 0..1023 m tile
    int j0 = nt * 128;
    int wm = wid >> 2;               // 0..1
    int wn = wid & 3;                // 0..3

    if (tid < 128) bias_s[tid] = b_ih[j0 + tid] + b_hh[j0 + tid];

    uint32_t s_base = smem_to_u32(Sb);

    int st_r[4], st_sw[4];
#pragma unroll
    for (int it = 0; it < 4; ++it) {
        int idx = tid + it * 256;        // 0..1023
        int r = idx >> 3;
        int kg = idx & 7;
        st_r[it] = r * 32 + kg;
        st_sw[it] = r * 8 + (kg ^ (r & 7));
    }

    const __nv_bfloat16* a_srcs[3] = {g_Ahi, g_Alo, g_Ahi};
    const __nv_bfloat16* b_srcs[3] = {g_Bhi, g_Bhi, g_Blo};

#define ISSUE_CHUNK(ch) do { \
        int _term = (ch) >> 2; \
        int _kk0 = ((ch) & 3) * 64; \
        const char* _gA = (const char*)(a_srcs[_term] + (size_t)mt * 128 * N_ + _kk0); \
        const char* _gB = (const char*)(b_srcs[_term] + (size_t)j0 * N_ + _kk0); \
        uint32_t _sa = s_base + ((ch) & 1) * 2u * TILE_BYTES; \
        uint32_t _sb = _sa + TILE_BYTES; \
        _Pragma("unroll") \
        for (int _it = 0; _it < 4; ++_it) { \
            CP_ASYNC16(_sa + (uint32_t)st_sw[_it] * 16u, _gA + (size_t)st_r[_it] * 16); \
            CP_ASYNC16(_sb + (uint32_t)st_sw[_it] * 16u, _gB + (size_t)st_r[_it] * 16); \
        } \
        CP_COMMIT(); \
    } while (0)

    int a_r15 = lane & 15;
    int a_kh  = lane >> 4;
    int b_row = ((lane & 16) >> 1) + (lane & 7);
    int b_kh  = (lane >> 3) & 1;

    float acc[4][4][4];
#pragma unroll
    for (int i = 0; i < 4; ++i)
#pragma unroll
        for (int j = 0; j < 4; ++j)
#pragma unroll
            for (int q = 0; q < 4; ++q) acc[i][j][q] = 0.f;

    ISSUE_CHUNK(0);

    for (int ch = 0; ch < 12; ++ch) {
        if (ch + 1 < 12) {
            ISSUE_CHUNK(ch + 1);
            CP_WAIT1();
        } else {
            CP_WAIT0();
        }
        __syncthreads();

        uint32_t as_base = s_base + (ch & 1) * 2u * TILE_BYTES;
        uint32_t bs_base = as_base + TILE_BYTES;

#pragma unroll
        for (int ks = 0; ks < 4; ++ks) {
            uint32_t afr[4][4];
            uint32_t bfr[4][2];
#pragma unroll
            for (int tm = 0; tm < 4; ++tm) {
                int row = wm * 64 + tm * 16 + a_r15;
                int c = (2 * ks + a_kh) ^ (a_r15 & 7);
                uint32_t addr = as_base + (uint32_t)(row * 64 + c * 8) * 2u;
                LDM_X4(afr[tm][0], afr[tm][1], afr[tm][2], afr[tm][3], addr);
            }
#pragma unroll
            for (int tn2 = 0; tn2 < 2; ++tn2) {
                int row = wn * 32 + tn2 * 16 + b_row;
                int c = (2 * ks + b_kh) ^ (b_row & 7);
                uint32_t addr = bs_base + (uint32_t)(row * 64 + c * 8) * 2u;
                uint32_t r0, r1, r2, r3;
                LDM_X4(r0, r1, r2, r3, addr);
                bfr[tn2 * 2 + 0][0] = r0; bfr[tn2 * 2 + 0][1] = r1;
                bfr[tn2 * 2 + 1][0] = r2; bfr[tn2 * 2 + 1][1] = r3;
            }
#pragma unroll
            for (int tm = 0; tm < 4; ++tm)
#pragma unroll
                for (int tn = 0; tn < 4; ++tn)
                    MMA16816(acc[tm][tn], afr[tm], bfr[tn]);
        }
        __syncthreads();
    }

    int qr = lane >> 2;
    int qc = (lane & 3) * 2;
#pragma unroll
    for (int tm = 0; tm < 4; ++tm) {
#pragma unroll
        for (int tn = 0; tn < 4; ++tn) {
            int colt = wn * 32 + tn * 8 + qc;
            size_t m0 = (size_t)mt * 128 + wm * 64 + tm * 16 + qr;
            float bx = bias_s[colt], by = bias_s[colt + 1];
            float2 v0 = make_float2(acc[tm][tn][0] + bx, acc[tm][tn][1] + by);
            float2 v1 = make_float2(acc[tm][tn][2] + bx, acc[tm][tn][3] + by);
            *(float2*)(g_G1 + m0 * G_ + j0 + colt) = v0;
            *(float2*)(g_G1 + (m0 + 8) * G_ + j0 + colt) = v1;
        }
    }
}

// ---------------- K4: persistent recurrence, tensor-core inner GEMM ------------
// R15 structure (proven 2913us) with ONE change: explicit software pipelining
// of the fragment loads in the mma section.
//   - All 8 A-LDSM of a kc batch-issued up front (latency overlaps B + mma).
//   - B fragments double-buffered: B(ks+1) loads issue before ks's 12 HMMA.
#define S_WHI 0
#define S_WLO 32768
#define S_AHI 65536
#define S_ALO 81920
#define S_GB  98304
#define S_TOT 107008

__global__ void __launch_bounds__(128, 1) k_recur(
        const float* __restrict__ Whh, float* __restrict__ out_enc) {
    extern __shared__ __align__(16) char smem[];
    uint32_t s_base = smem_to_u32(smem);
    float* gbuf = (float*)(smem + S_GB);      // [32][68] fp32 gate bounce

    int tid = threadIdx.x;            // 128 = 4 warps
    int lane = tid & 31;
    int wid = tid >> 5;
    int wm = wid & 1;                 // m half (16 batches)
    int wn = wid >> 1;                // n half (32 gate cols)
    int b0 = blockIdx.x * 32;
    int h0 = blockIdx.y * 16;
    int grp = blockIdx.x;

    // Build W bf16 hi/lo subtiles once (layout proven R12).
    for (int idx = tid; idx < 4096; idx += 128) {
        int n = idx >> 6;             // 0..63
        int kq = idx & 63;            // float4 index along k
        int hid = n >> 2, q = n & 3;
        float4 v = *(const float4*)(Whh + (size_t)(q * H_ + h0 + hid) * N_ + kq * 4);
        uint2 hi, lo;
        split4(v, hi, lo);
        int kc = kq >> 4, kk = kq & 15, kg = kk >> 1, half = kk & 1;
        uint32_t off = (uint32_t)(kc * 8192 + n * 128 + ((kg ^ (n & 7)) << 4) + half * 8);
        *(uint2*)(smem + S_WHI + off) = hi;
        *(uint2*)(smem + S_WLO + off) = lo;
    }

    // ldmatrix lane precompute (identical to K3)
    int a_r15 = lane & 15;
    int a_kh  = lane >> 4;
    int b_row = ((lane & 16) >> 1) + (lane & 7);
    int b_kh  = (lane >> 3) & 1;

    // kc-ordered staging indices: per kc, 256 granules; thread covers 2 per plane.
    int stg_b[4][2], stg_kg[4][2];
#pragma unroll
    for (int kc = 0; kc < 4; ++kc)
#pragma unroll
        for (int sub = 0; sub < 2; ++sub) {
            int idx = sub * 128 + tid;    // 0..255 within chunk
            stg_b[kc][sub] = idx >> 3;
            stg_kg[kc][sub] = idx & 7;
        }

    // epilogue mapping: thread owns batch eb, hids [eh4*4, eh4*4+4)
    int eb  = tid & 31;
    int eh4 = tid >> 5;

    float creg[4] = {0.f, 0.f, 0.f, 0.f};
    __syncthreads();

    // G1 prefetch for t=0: g1s[q*4+j]
    float g1s[16];
#pragma unroll
    for (int q = 0; q < 4; ++q) {
        float4 v = __ldcg((const float4*)(g_G1 + ((size_t)(b0 + eb)) * G_ + q * 256 + h0 + eh4 * 4));
        g1s[q * 4 + 0] = v.x; g1s[q * 4 + 1] = v.y;
        g1s[q * 4 + 2] = v.z; g1s[q * 4 + 3] = v.w;
    }

    for (int t = 0; t < T_; ++t) {
        // stage h bf16 planes -> swizzled A subtiles, one commit group PER kc
        const char* srcHi = (const char*)(g_hbf[t & 1][0] + (size_t)b0 * H_);
        const char* srcLo = (const char*)(g_hbf[t & 1][1] + (size_t)b0 * H_);
#pragma unroll
        for (int kc = 0; kc < 4; ++kc) {
#pragma unroll
            for (int sub = 0; sub < 2; ++sub) {
                int b = stg_b[kc][sub], kg = stg_kg[kc][sub];
                uint32_t doff = (uint32_t)(kc * 4096 + b * 128 + ((kg ^ (b & 7)) << 4));
                size_t soff = (size_t)b * 512 + kc * 128 + kg * 16;
                CP_ASYNC16(s_base + S_AHI + doff, srcHi + soff);
                CP_ASYNC16(s_base + S_ALO + doff, srcLo + soff);
            }
            CP_COMMIT();
        }

        // D = h @ W^T, 3-term bf16 split; per-kc pipelined wait +
        // software-pipelined fragment loads.
        float cfr[4][4];
#pragma unroll
        for (int tn = 0; tn < 4; ++tn)
#pragma unroll
            for (int q = 0; q < 4; ++q) cfr[tn][q] = 0.f;

#pragma unroll
        for (int kc = 0; kc < 4; ++kc) {
            if (kc == 0)      CP_WAITN(3);
            else if (kc == 1) CP_WAITN(2);
            else if (kc == 2) CP_WAITN(1);
            else              CP_WAITN(0);
            __syncthreads();

            uint32_t aHiB = s_base + S_AHI + kc * 4096;
            uint32_t aLoB = s_base + S_ALO + kc * 4096;
            uint32_t bHiB = s_base + S_WHI + kc * 8192;
            uint32_t bLoB = s_base + S_WLO + kc * 8192;

            // batch-issue ALL A fragments for this kc (8 LDSM)
            uint32_t ahi[4][4], alo[4][4];
#pragma unroll
            for (int ks = 0; ks < 4; ++ks) {
                int ac = (2 * ks + a_kh) ^ (a_r15 & 7);
                uint32_t aoff = (uint32_t)((wm * 16 + a_r15) * 128 + ac * 16);
                LDM_X4(ahi[ks][0], ahi[ks][1], ahi[ks][2], ahi[ks][3], aHiB + aoff);
                LDM_X4(alo[ks][0], alo[ks][1], alo[ks][2], alo[ks][3], aLoB + aoff);
            }

            // B fragments double-buffered: load ks+1 before ks's MMAs
            uint32_t bhi[2][4][2], blo[2][4][2];
#define LOAD_B(buf, ks_) do { \
    _Pragma("unroll") \
    for (int tn2 = 0; tn2 < 2; ++tn2) { \
        int row = wn * 32 + tn2 * 16 + b_row; \
        int bc = (2 * (ks_) + b_kh) ^ (b_row & 7); \
        uint32_t boff = (uint32_t)(row * 128 + bc * 16); \
        uint32_t r0, r1, r2, r3; \
        LDM_X4(r0, r1, r2, r3, bHiB + boff); \
        bhi[buf][tn2 * 2 + 0][0] = r0; bhi[buf][tn2 * 2 + 0][1] = r1; \
        bhi[buf][tn2 * 2 + 1][0] = r2; bhi[buf][tn2 * 2 + 1][1] = r3; \
        LDM_X4(r0, r1, r2, r3, bLoB + boff); \
        blo[buf][tn2 * 2 + 0][0] = r0; blo[buf][tn2 * 2 + 0][1] = r1; \
        blo[buf][tn2 * 2 + 1][0] = r2; blo[buf][tn2 * 2 + 1][1] = r3; \
    } \
} while (0)

            LOAD_B(0, 0);
#pragma unroll
            for (int ks = 0; ks < 4; ++ks) {
                int cur = ks & 1;
                if (ks < 3) {
                    int nxt = cur ^ 1;
                    if (ks == 0) LOAD_B(1, 1);
                    else if (ks == 1) LOAD_B(0, 2);
                    else LOAD_B(1, 3);
                    (void)nxt;
                }
#pragma unroll
                for (int tn = 0; tn < 4; ++tn) MMA16816(cfr[tn], ahi[ks], bhi[cur][tn]);
#pragma unroll
                for (int tn = 0; tn < 4; ++tn) MMA16816(cfr[tn], alo[ks], bhi[cur][tn]);
#pragma unroll
                for (int tn = 0; tn < 4; ++tn) MMA16816(cfr[tn], ahi[ks], blo[cur][tn]);
            }
#undef LOAD_B
        }

        // scatter c-frags to gate bounce buffer
        int qr = lane >> 2, qc = (lane & 3) * 2;
#pragma unroll
        for (int tn = 0; tn < 4; ++tn) {
            int col = wn * 32 + tn * 8 + qc;
            int r0 = wm * 16 + qr;
            *(float2*)&gbuf[r0 * 68 + col] = make_float2(cfr[tn][0], cfr[tn][1]);
            *(float2*)&gbuf[(r0 + 8) * 68 + col] = make_float2(cfr[tn][2], cfr[tn][3]);
        }
        __syncthreads();

        // LSTM epilogue: thread reads 16 contiguous gates (4 hid x 4 q)
        float ga[16];
#pragma unroll
        for (int j4 = 0; j4 < 4; ++j4) {
            float4 v = *(const float4*)&gbuf[eb * 68 + eh4 * 16 + j4 * 4];
            ga[j4 * 4 + 0] = v.x; ga[j4 * 4 + 1] = v.y;
            ga[j4 * 4 + 2] = v.z; ga[j4 * 4 + 3] = v.w;
        }
        float hn[4];
#pragma unroll
        for (int j = 0; j < 4; ++j) {
            float gi = ga[j * 4 + 0] + g1s[0 * 4 + j];
            float gf = ga[j * 4 + 1] + g1s[1 * 4 + j];
            float gg = ga[j * 4 + 2] + g1s[2 * 4 + j];
            float go = ga[j * 4 + 3] + g1s[3 * 4 + j];
            float cc = fmaf(sigf(gf), creg[j], sigf(gi) * tanhfast(gg));
            creg[j] = cc;
            hn[j] = sigf(go) * tanhfast(cc);
        }
        // producer-side bf16 hi/lo split; h stores FIRST (peers wait on these)
        float4 hv = make_float4(hn[0], hn[1], hn[2], hn[3]);
        uint2 hiv, lov;
        split4(hv, hiv, lov);
        size_t hoff = (size_t)(b0 + eb) * H_ + h0 + eh4 * 4;
        __stcg((uint2*)(g_hbf[(t + 1) & 1][0] + hoff), hiv);
        __stcg((uint2*)(g_hbf[(t + 1) & 1][1] + hoff), lov);

        if (t + 1 < T_) {
            // ---- EARLY arrival: release h stores, signal, then fill the wait
            //      window with the out_enc store + G1 prefetch ----
            __threadfence();
            __syncthreads();
            if (tid == 0) atomicAdd(&g_cnt_grp[grp * 32], 1u);

            *(float4*)(out_enc + ((size_t)(b0 + eb) * T_ + t) * H_ + h0 + eh4 * 4) = hv;
#pragma unroll
            for (int q = 0; q < 4; ++q) {
                float4 v = __ldcg((const float4*)(g_G1 + ((size_t)(t + 1) * B_ + b0 + eb) * G_ + q * 256 + h0 + eh4 * 4));
                g1s[q * 4 + 0] = v.x; g1s[q * 4 + 1] = v.y;
                g1s[q * 4 + 2] = v.z; g1s[q * 4 + 3] = v.w;
            }

            unsigned target = (unsigned)(t + 1) * 16u;
            volatile unsigned* cp = &g_cnt_grp[grp * 32];
            while (*cp < target) { __nanosleep(32); }
            __threadfence();
        } else {
            *(float4*)(out_enc + ((size_t)(b0 + eb) * T_ + t) * H_ + h0 + eh4 * 4) = hv;
        }
    }
}

// ---------------- launch ----------------
extern "C" void kernel_launch(void* const* d_in, const int* in_sizes, int n_in,
                              void* d_out, int out_size) {
    const float* input  = (const float*)d_in[0];
    const float* W_ih   = (const float*)d_in[1];
    const float* W_hh   = (const float*)d_in[2];
    const float* b_ih   = (const float*)d_in[3];
    const float* b_hh   = (const float*)d_in[4];
    const float* attn_w = (const float*)d_in[5];
    float* out = (float*)d_out;

    cudaFuncSetAttribute(k_recur, cudaFuncAttributeMaxDynamicSharedMemorySize, S_TOT);

    // K1: attention weights (+ zero h planes, zero group counters)
    k_attn<<<B_, N_>>>(input, attn_w);
    // K2: weighted input -> output region 0 + bf16 hi/lo staging
    k_weighted<<<B_ * T_, N_>>>(input, out);
    // K2b: W_ih bf16 hi/lo
    k_convB<<<G_, N_>>>(W_ih);
    // K3: HMMA split-bf16 GEMM into g_G1, cp.async double-buffered
    dim3 g3(8, 1024);
    k_gemm_mma<<<g3, 256>>>(b_ih, b_hh);
    // K4: persistent recurrence -> output region 1 (sw-pipelined fragments)
    dim3 g4(8, 16);
    k_recur<<<g4, 128, S_TOT>>>(W_hh, out + ENC_OFF);
}